// round 6
// baseline (speedup 1.0000x reference)
#include <cuda_runtime.h>
#include <cuda_bf16.h>

// CenterLoss: loss = LAMBDA_C * mean_b sum_d (features[b,d] - centers[labels[b],d])^2
// B=65536, D=256, C=100000.
//
// R5: single kernel, last-block-finalizes — but unlike R3:
//  - per-block partial goes to a DISTINCT address (plain STG, no atomic serialization)
//  - completion counter uses one atom.add.acq_rel.gpu (release orders the STG,
//    acquire orders the finalizer's reads) -> no __threadfence / CCTL.IVALL,
//    no waiting on a serialized same-address atomic queue.
//  - finalizer block reduces the 1024 L2-hot partials in a fixed-order double
//    tree -> bitwise deterministic regardless of which block runs it.

#define BATCH     65536
#define FEAT_DIM  256
#define LAMBDA_C  1.0

#define WARPS_PER_BLOCK 8
#define ROWS_PER_WARP   8
#define ROWS_PER_BLOCK  (WARPS_PER_BLOCK * ROWS_PER_WARP)      // 64
#define NBLOCKS         (BATCH / ROWS_PER_BLOCK)               // 1024

__device__ float        g_partials[NBLOCKS];   // overwritten every replay
__device__ unsigned int g_done;                // zero-init; reset by finalizer

__global__ __launch_bounds__(256, 8)
void center_loss_kernel(const float* __restrict__ features,
                        const int*   __restrict__ labels,
                        const float* __restrict__ centers,
                        float*       __restrict__ out) {
    const int warp = threadIdx.x >> 5;
    const int lane = threadIdx.x & 31;
    const int row0 = blockIdx.x * ROWS_PER_BLOCK + warp * ROWS_PER_WARP;

    float acc = 0.0f;

    #pragma unroll
    for (int r = 0; r < ROWS_PER_WARP; r++) {
        const int row = row0 + r;
        const float4* frow = reinterpret_cast<const float4*>(features + (size_t)row * FEAT_DIM);
        const int lab = __ldg(&labels[row]);
        const float4* crow = reinterpret_cast<const float4*>(centers + (size_t)lab * FEAT_DIM);

        float4 a0 = __ldcs(&frow[lane]);        // features: streaming
        float4 a1 = __ldcs(&frow[lane + 32]);
        float4 b0 = __ldg(&crow[lane]);         // centers: L2 reuse
        float4 b1 = __ldg(&crow[lane + 32]);

        float d;
        d = a0.x - b0.x; acc = fmaf(d, d, acc);
        d = a0.y - b0.y; acc = fmaf(d, d, acc);
        d = a0.z - b0.z; acc = fmaf(d, d, acc);
        d = a0.w - b0.w; acc = fmaf(d, d, acc);
        d = a1.x - b1.x; acc = fmaf(d, d, acc);
        d = a1.y - b1.y; acc = fmaf(d, d, acc);
        d = a1.z - b1.z; acc = fmaf(d, d, acc);
        d = a1.w - b1.w; acc = fmaf(d, d, acc);
    }

    // warp reduce (float)
    #pragma unroll
    for (int off = 16; off > 0; off >>= 1)
        acc += __shfl_xor_sync(0xffffffffu, acc, off);

    __shared__ float s[WARPS_PER_BLOCK];
    __shared__ int   s_last;
    if (lane == 0) s[warp] = acc;
    if (threadIdx.x == 0) s_last = 0;
    __syncthreads();

    if (threadIdx.x == 0) {
        float t = 0.0f;
        #pragma unroll
        for (int i = 0; i < WARPS_PER_BLOCK; i++) t += s[i];

        // Distinct-address store: no serialization across blocks.
        g_partials[blockIdx.x] = t;

        // acq_rel atomic: release orders the STG above before the increment;
        // acquire orders the finalizer's reads after observing all increments.
        unsigned int prev;
        asm volatile("atom.add.acq_rel.gpu.global.u32 %0, [%1], 1;"
                     : "=r"(prev) : "l"(&g_done) : "memory");
        if (prev == NBLOCKS - 1) s_last = 1;
    }
    __syncthreads();

    if (s_last) {
        // Finalizer block: reduce 1024 L2-hot partials in a fixed-order
        // double tree (deterministic regardless of which block executes).
        const int tid = threadIdx.x;
        double acc2 = 0.0;
        #pragma unroll
        for (int i = 0; i < NBLOCKS / 256; i++)
            acc2 += (double)g_partials[tid + i * 256];   // volatile not needed: acquire above

        #pragma unroll
        for (int off = 16; off > 0; off >>= 1)
            acc2 += __shfl_xor_sync(0xffffffffu, acc2, off);

        __shared__ double sd[WARPS_PER_BLOCK];
        if (lane == 0) sd[warp] = acc2;
        __syncthreads();

        if (threadIdx.x == 0) {
            double tt = 0.0;
            #pragma unroll
            for (int i = 0; i < WARPS_PER_BLOCK; i++) tt += sd[i];
            out[0] = (float)(LAMBDA_C * (tt / (double)BATCH));
            g_done = 0u;   // restore for next graph replay
        }
    }
}

extern "C" void kernel_launch(void* const* d_in, const int* in_sizes, int n_in,
                              void* d_out, int out_size) {
    const float* features = (const float*)d_in[0];
    const int*   labels   = (const int*)d_in[1];
    const float* centers  = (const float*)d_in[2];
    float* out = (float*)d_out;

    center_loss_kernel<<<NBLOCKS, 256>>>(features, labels, centers, out);
}

// round 7
// speedup vs baseline: 1.0017x; 1.0017x over previous
#include <cuda_runtime.h>
#include <cuda_bf16.h>

// CenterLoss: loss = LAMBDA_C * mean_b sum_d (features[b,d] - centers[labels[b],d])^2
// B=65536, D=256, C=100000.
//
// R6: single kernel with a dedicated WATCHER block (bid==NBLOCKS).
// Workers (bids 0..1023) = proven R2 loop + tail of exactly:
//   STG partial to distinct address + fire-and-forget red.release counter tick.
// Nothing on the worker critical path waits (R3/R5 post-mortems: returning /
// fenced atomics on workers cost 1.4-8.5us). Watcher spins on ld.acquire of
// the counter, then does a fixed-order double-tree reduction (deterministic),
// writes out, resets counter. Single wave: 1025 blocks < 1184 resident slots.

#define BATCH     65536
#define FEAT_DIM  256
#define LAMBDA_C  1.0

#define WARPS_PER_BLOCK 8
#define ROWS_PER_WARP   8
#define ROWS_PER_BLOCK  (WARPS_PER_BLOCK * ROWS_PER_WARP)      // 64
#define NBLOCKS         (BATCH / ROWS_PER_BLOCK)               // 1024 worker blocks

__device__ float        g_partials[NBLOCKS];   // fully overwritten every replay
__device__ unsigned int g_done;                // zero-init; reset by watcher

__global__ __launch_bounds__(256, 8)
void center_loss_kernel(const float* __restrict__ features,
                        const int*   __restrict__ labels,
                        const float* __restrict__ centers,
                        float*       __restrict__ out) {
    const int warp = threadIdx.x >> 5;
    const int lane = threadIdx.x & 31;

    if (blockIdx.x == NBLOCKS) {
        // ── Watcher block: wait for all worker ticks, then finalize ──
        if (threadIdx.x == 0) {
            unsigned int v;
            do {
                asm volatile("ld.acquire.gpu.global.u32 %0, [%1];"
                             : "=r"(v) : "l"(&g_done) : "memory");
            } while (v != NBLOCKS);
        }
        __syncthreads();   // all 256 threads wait for completion signal

        const int tid = threadIdx.x;
        double acc2 = 0.0;
        #pragma unroll
        for (int i = 0; i < NBLOCKS / 256; i++)
            acc2 += (double)g_partials[tid + i * 256];

        #pragma unroll
        for (int off = 16; off > 0; off >>= 1)
            acc2 += __shfl_xor_sync(0xffffffffu, acc2, off);

        __shared__ double sd[WARPS_PER_BLOCK];
        if (lane == 0) sd[warp] = acc2;
        __syncthreads();

        if (threadIdx.x == 0) {
            double tt = 0.0;
            #pragma unroll
            for (int i = 0; i < WARPS_PER_BLOCK; i++) tt += sd[i];
            out[0] = (float)(LAMBDA_C * (tt / (double)BATCH));
            g_done = 0u;   // restore for next graph replay
        }
        return;
    }

    // ── Worker block: identical to the proven R2 loop ──
    const int row0 = blockIdx.x * ROWS_PER_BLOCK + warp * ROWS_PER_WARP;
    float acc = 0.0f;

    #pragma unroll
    for (int r = 0; r < ROWS_PER_WARP; r++) {
        const int row = row0 + r;
        const float4* frow = reinterpret_cast<const float4*>(features + (size_t)row * FEAT_DIM);
        const int lab = __ldg(&labels[row]);
        const float4* crow = reinterpret_cast<const float4*>(centers + (size_t)lab * FEAT_DIM);

        float4 a0 = __ldcs(&frow[lane]);        // features: streaming
        float4 a1 = __ldcs(&frow[lane + 32]);
        float4 b0 = __ldg(&crow[lane]);         // centers: L2 reuse
        float4 b1 = __ldg(&crow[lane + 32]);

        float d;
        d = a0.x - b0.x; acc = fmaf(d, d, acc);
        d = a0.y - b0.y; acc = fmaf(d, d, acc);
        d = a0.z - b0.z; acc = fmaf(d, d, acc);
        d = a0.w - b0.w; acc = fmaf(d, d, acc);
        d = a1.x - b1.x; acc = fmaf(d, d, acc);
        d = a1.y - b1.y; acc = fmaf(d, d, acc);
        d = a1.z - b1.z; acc = fmaf(d, d, acc);
        d = a1.w - b1.w; acc = fmaf(d, d, acc);
    }

    #pragma unroll
    for (int off = 16; off > 0; off >>= 1)
        acc += __shfl_xor_sync(0xffffffffu, acc, off);

    __shared__ float s[WARPS_PER_BLOCK];
    if (lane == 0) s[warp] = acc;
    __syncthreads();

    if (threadIdx.x == 0) {
        float t = 0.0f;
        #pragma unroll
        for (int i = 0; i < WARPS_PER_BLOCK; i++) t += s[i];

        // Distinct-address partial store, then fire-and-forget release tick.
        // Nothing here returns a value or requires a wait.
        g_partials[blockIdx.x] = t;
        asm volatile("red.release.gpu.global.add.u32 [%0], 1;"
                     :: "l"(&g_done) : "memory");
    }
}

extern "C" void kernel_launch(void* const* d_in, const int* in_sizes, int n_in,
                              void* d_out, int out_size) {
    const float* features = (const float*)d_in[0];
    const int*   labels   = (const int*)d_in[1];
    const float* centers  = (const float*)d_in[2];
    float* out = (float*)d_out;

    center_loss_kernel<<<NBLOCKS + 1, 256>>>(features, labels, centers, out);
}